// round 1
// baseline (speedup 1.0000x reference)
#include <cuda_runtime.h>
#include <cuda_bf16.h>
#include <math.h>

#define N_NODES 20000
#define N_EDGES 160000
#define D 512
#define N_GRAPHS 16
#define NODES_PER_GRAPH 1250

// Scratch (static __device__ — no allocations allowed)
__device__ float g_h[N_NODES * D];     // layer activations
__device__ float g_agg[N_NODES * D];   // aggregation buffer
__device__ float g_onorm[N_NODES];     // out-degree^{-1/2} (also used as deg accumulator)
__device__ float g_inorm[N_NODES];     // in-degree^{-1/2}

// ---------------------------------------------------------------------------
// Zero kernels
// ---------------------------------------------------------------------------
__global__ void zero_norms_kernel() {
    int i = blockIdx.x * blockDim.x + threadIdx.x;
    if (i < N_NODES) { g_onorm[i] = 0.0f; g_inorm[i] = 0.0f; }
}

__global__ void zero_agg_kernel() {
    // N_NODES*D/4 float4 = 2,560,000
    float4* p = reinterpret_cast<float4*>(g_agg);
    int n4 = (N_NODES * D) / 4;
    for (int i = blockIdx.x * blockDim.x + threadIdx.x; i < n4; i += gridDim.x * blockDim.x) {
        p[i] = make_float4(0.f, 0.f, 0.f, 0.f);
    }
}

// ---------------------------------------------------------------------------
// Degrees + norms
// ---------------------------------------------------------------------------
__global__ void degree_kernel(const int* __restrict__ src, const int* __restrict__ dst) {
    int e = blockIdx.x * blockDim.x + threadIdx.x;
    if (e < N_EDGES) {
        atomicAdd(&g_onorm[src[e]], 1.0f);
        atomicAdd(&g_inorm[dst[e]], 1.0f);
    }
}

__global__ void norm_kernel() {
    int i = blockIdx.x * blockDim.x + threadIdx.x;
    if (i < N_NODES) {
        float od = g_onorm[i];
        float id = g_inorm[i];
        g_onorm[i] = od > 0.0f ? 1.0f / sqrtf(od) : 0.0f;
        g_inorm[i] = id > 0.0f ? 1.0f / sqrtf(id) : 0.0f;
    }
}

// ---------------------------------------------------------------------------
// Scatter: agg[dst] += h[src] * out_norm[src]
// One block (128 threads) per edge; each thread handles one float4.
// ---------------------------------------------------------------------------
__global__ void scatter_kernel(const float* __restrict__ h,
                               const int* __restrict__ src,
                               const int* __restrict__ dst) {
    int e = blockIdx.x;
    int s = src[e];
    int d = dst[e];
    float w = g_onorm[s];
    const float4* hv = reinterpret_cast<const float4*>(h);
    float4 v = hv[(size_t)s * (D / 4) + threadIdx.x];
    v.x *= w; v.y *= w; v.z *= w; v.w *= w;
    float4* dptr = reinterpret_cast<float4*>(g_agg) + (size_t)d * (D / 4) + threadIdx.x;
    asm volatile("red.global.add.v4.f32 [%0], {%1, %2, %3, %4};"
                 :: "l"(dptr), "f"(v.x), "f"(v.y), "f"(v.z), "f"(v.w)
                 : "memory");
}

// ---------------------------------------------------------------------------
// GEMM: C[M,512] = (A * in_norm[row]) @ W[512,512] + b, optional ReLU
// BM=128, BN=128, BK=16, 256 threads, 8x8 per thread.
// ---------------------------------------------------------------------------
#define BM 128
#define BN 128
#define BK 16
#define TM 8
#define TN 8

__global__ __launch_bounds__(256, 2)
void gemm_bias_act_kernel(const float* __restrict__ A,
                          const float* __restrict__ W,
                          const float* __restrict__ bias,
                          float* __restrict__ C,
                          int M, int apply_relu) {
    __shared__ float As[BM][BK];
    __shared__ float Bs[BK][BN];

    int tid = threadIdx.x;
    int block_row = blockIdx.y * BM;
    int block_col = blockIdx.x * BN;
    int tm = (tid / 16) * TM;   // 0..120
    int tn = (tid % 16) * TN;   // 0..120

    float acc[TM][TN];
#pragma unroll
    for (int i = 0; i < TM; i++)
#pragma unroll
        for (int j = 0; j < TN; j++) acc[i][j] = 0.0f;

    for (int k0 = 0; k0 < D; k0 += BK) {
        // Load A tile (128x16), scaled by in_norm[row]. 512 float4 / 256 thr = 2 each.
#pragma unroll
        for (int i = 0; i < 2; i++) {
            int f = tid + i * 256;            // 0..511
            int r = f >> 2;                   // row within tile 0..127
            int kk = (f & 3) * 4;             // 0,4,8,12
            int grow = block_row + r;
            float4 v = make_float4(0.f, 0.f, 0.f, 0.f);
            if (grow < M) {
                v = *reinterpret_cast<const float4*>(&A[(size_t)grow * D + k0 + kk]);
                float s = g_inorm[grow];
                v.x *= s; v.y *= s; v.z *= s; v.w *= s;
            }
            *reinterpret_cast<float4*>(&As[r][kk]) = v;
        }
        // Load W tile (16x128). 512 float4 / 256 thr = 2 each.
#pragma unroll
        for (int i = 0; i < 2; i++) {
            int f = tid + i * 256;
            int r = f >> 5;                   // 0..15
            int cc = (f & 31) * 4;            // 0..124
            float4 v = *reinterpret_cast<const float4*>(&W[(size_t)(k0 + r) * D + block_col + cc]);
            *reinterpret_cast<float4*>(&Bs[r][cc]) = v;
        }
        __syncthreads();

#pragma unroll
        for (int k = 0; k < BK; k++) {
            float a[TM], b[TN];
#pragma unroll
            for (int i = 0; i < TM; i++) a[i] = As[tm + i][k];
#pragma unroll
            for (int j = 0; j < TN; j += 4) {
                float4 bv = *reinterpret_cast<const float4*>(&Bs[k][tn + j]);
                b[j] = bv.x; b[j + 1] = bv.y; b[j + 2] = bv.z; b[j + 3] = bv.w;
            }
#pragma unroll
            for (int i = 0; i < TM; i++)
#pragma unroll
                for (int j = 0; j < TN; j++)
                    acc[i][j] = fmaf(a[i], b[j], acc[i][j]);
        }
        __syncthreads();
    }

    // Epilogue: bias + optional relu
#pragma unroll
    for (int i = 0; i < TM; i++) {
        int row = block_row + tm + i;
        if (row >= M) continue;
#pragma unroll
        for (int j = 0; j < TN; j += 4) {
            int col = block_col + tn + j;
            float4 bv = *reinterpret_cast<const float4*>(&bias[col]);
            float4 o;
            o.x = acc[i][j + 0] + bv.x;
            o.y = acc[i][j + 1] + bv.y;
            o.z = acc[i][j + 2] + bv.z;
            o.w = acc[i][j + 3] + bv.w;
            if (apply_relu) {
                o.x = fmaxf(o.x, 0.f); o.y = fmaxf(o.y, 0.f);
                o.z = fmaxf(o.z, 0.f); o.w = fmaxf(o.w, 0.f);
            }
            *reinterpret_cast<float4*>(&C[(size_t)row * D + col]) = o;
        }
    }
}

// ---------------------------------------------------------------------------
// Mean pool per graph: graphs are contiguous blocks of 1250 nodes.
// grid (16, 4), block 128: each thread sums one column over 1250 rows.
// ---------------------------------------------------------------------------
__global__ void pool_kernel(float* __restrict__ out) {
    int g = blockIdx.x;
    int c = blockIdx.y * 128 + threadIdx.x;
    const float* base = g_h + (size_t)g * NODES_PER_GRAPH * D;
    float s0 = 0.f, s1 = 0.f;
#pragma unroll 4
    for (int i = 0; i < NODES_PER_GRAPH; i += 2) {
        s0 += base[(size_t)i * D + c];
        s1 += base[(size_t)(i + 1) * D + c];
    }
    out[g * D + c] = (s0 + s1) * (1.0f / (float)NODES_PER_GRAPH);
}

// ---------------------------------------------------------------------------
// Launch
// ---------------------------------------------------------------------------
extern "C" void kernel_launch(void* const* d_in, const int* in_sizes, int n_in,
                              void* d_out, int out_size) {
    const float* feat = (const float*)d_in[0];
    const int* src = (const int*)d_in[1];
    const int* dst = (const int*)d_in[2];
    // d_in[3] = graph_ids (unused: graphs are contiguous 1250-node blocks)
    const float* W[4] = {(const float*)d_in[4], (const float*)d_in[6],
                         (const float*)d_in[8], (const float*)d_in[10]};
    const float* B[4] = {(const float*)d_in[5], (const float*)d_in[7],
                         (const float*)d_in[9], (const float*)d_in[11]};
    float* out = (float*)d_out;

    float* h_ptr = nullptr;
    cudaGetSymbolAddress((void**)&h_ptr, g_h);
    float* agg_ptr = nullptr;
    cudaGetSymbolAddress((void**)&agg_ptr, g_agg);

    // Degrees + norms
    zero_norms_kernel<<<(N_NODES + 255) / 256, 256>>>();
    degree_kernel<<<(N_EDGES + 255) / 256, 256>>>(src, dst);
    norm_kernel<<<(N_NODES + 255) / 256, 256>>>();

    dim3 gemm_grid(D / BN, (N_NODES + BM - 1) / BM);

    for (int layer = 0; layer < 4; layer++) {
        const float* hin = (layer == 0) ? feat : h_ptr;
        zero_agg_kernel<<<1024, 256>>>();
        scatter_kernel<<<N_EDGES, D / 4>>>(hin, src, dst);
        gemm_bias_act_kernel<<<gemm_grid, 256>>>(agg_ptr, W[layer], B[layer],
                                                 h_ptr, N_NODES,
                                                 layer < 3 ? 1 : 0);
    }

    pool_kernel<<<dim3(N_GRAPHS, D / 128), 128>>>(out);
}

// round 3
// speedup vs baseline: 2.1933x; 2.1933x over previous
#include <cuda_runtime.h>
#include <cuda_bf16.h>
#include <cstdint>
#include <math.h>

#define N_NODES 20000
#define N_EDGES 160000
#define D 512
#define N_GRAPHS 16
#define NODES_PER_GRAPH 1250
#define N_LAYERS 4

// ---------------------------------------------------------------------------
// Device scratch (static globals — no allocations allowed)
// ---------------------------------------------------------------------------
__device__ float g_h[N_NODES * D];                 // layer output activations (fp32)
__device__ __nv_bfloat16 g_a0[N_NODES * D];        // aggregated input, bf16 hi
__device__ __nv_bfloat16 g_a1[N_NODES * D];        // aggregated input, bf16 lo
__device__ __nv_bfloat16 g_wt0[N_LAYERS * D * D];  // W^T bf16 hi, [layer][n][k]
__device__ __nv_bfloat16 g_wt1[N_LAYERS * D * D];  // W^T bf16 lo
__device__ float g_onorm[N_NODES];
__device__ float g_inorm[N_NODES];
__device__ int g_outdeg[N_NODES];
__device__ int g_indeg[N_NODES];
__device__ int g_rowoff[N_NODES + 1];
__device__ int g_cursor[N_NODES];
__device__ int g_csr[N_EDGES];                     // src ids grouped by dst

__device__ __forceinline__ uint32_t smem_u32(const void* p) {
    uint32_t a;
    asm("{ .reg .u64 t; cvta.to.shared.u64 t, %1; cvt.u32.u64 %0, t; }" : "=r"(a) : "l"(p));
    return a;
}

__device__ __forceinline__ void cp_async_16(uint32_t dst, const void* src, int src_size) {
    asm volatile("cp.async.cg.shared.global [%0], [%1], 16, %2;"
                 :: "r"(dst), "l"(src), "r"(src_size) : "memory");
}

__device__ __forceinline__ void ldsm_x4(uint32_t* r, uint32_t addr) {
    asm volatile("ldmatrix.sync.aligned.m8n8.x4.shared.b16 {%0,%1,%2,%3}, [%4];"
                 : "=r"(r[0]), "=r"(r[1]), "=r"(r[2]), "=r"(r[3]) : "r"(addr));
}

__device__ __forceinline__ void mma_16816(float* d, const uint32_t* a,
                                          uint32_t b0, uint32_t b1) {
    asm volatile(
        "mma.sync.aligned.m16n8k16.row.col.f32.bf16.bf16.f32 "
        "{%0,%1,%2,%3}, {%4,%5,%6,%7}, {%8,%9}, {%0,%1,%2,%3};"
        : "+f"(d[0]), "+f"(d[1]), "+f"(d[2]), "+f"(d[3])
        : "r"(a[0]), "r"(a[1]), "r"(a[2]), "r"(a[3]), "r"(b0), "r"(b1));
}

// ---------------------------------------------------------------------------
// Graph preprocessing
// ---------------------------------------------------------------------------
__global__ void zero_deg_kernel() {
    int i = blockIdx.x * blockDim.x + threadIdx.x;
    if (i < N_NODES) { g_outdeg[i] = 0; g_indeg[i] = 0; }
}

__global__ void degree_kernel(const int* __restrict__ src, const int* __restrict__ dst) {
    int e = blockIdx.x * blockDim.x + threadIdx.x;
    if (e < N_EDGES) {
        atomicAdd(&g_outdeg[src[e]], 1);
        atomicAdd(&g_indeg[dst[e]], 1);
    }
}

__global__ void norm_kernel() {
    int i = blockIdx.x * blockDim.x + threadIdx.x;
    if (i < N_NODES) {
        int od = g_outdeg[i];
        int id = g_indeg[i];
        g_onorm[i] = od > 0 ? 1.0f / sqrtf((float)od) : 0.0f;
        g_inorm[i] = id > 0 ? 1.0f / sqrtf((float)id) : 0.0f;
    }
}

__global__ void scan_kernel() {
    const int CH = (N_NODES + 1023) / 1024;  // 20
    __shared__ int sm[1024];
    int tid = threadIdx.x;
    int base = tid * CH;
    int local[CH];
    int s = 0;
#pragma unroll
    for (int i = 0; i < CH; i++) {
        int idx = base + i;
        int v = (idx < N_NODES) ? g_indeg[idx] : 0;
        local[i] = s;
        s += v;
    }
    sm[tid] = s;
    __syncthreads();
    for (int off = 1; off < 1024; off <<= 1) {
        int v = (tid >= off) ? sm[tid - off] : 0;
        __syncthreads();
        sm[tid] += v;
        __syncthreads();
    }
    int excl = sm[tid] - s;
#pragma unroll
    for (int i = 0; i < CH; i++) {
        int idx = base + i;
        if (idx < N_NODES) {
            int v = excl + local[i];
            g_rowoff[idx] = v;
            g_cursor[idx] = v;
        }
    }
    if (tid == 1023) g_rowoff[N_NODES] = sm[1023];
}

__global__ void fill_kernel(const int* __restrict__ src, const int* __restrict__ dst) {
    int e = blockIdx.x * blockDim.x + threadIdx.x;
    if (e < N_EDGES) {
        int d = dst[e];
        int pos = atomicAdd(&g_cursor[d], 1);
        g_csr[pos] = src[e];
    }
}

// ---------------------------------------------------------------------------
// W transpose + bf16 split: WT[layer][n][k] = W[k][n], hi/lo
// ---------------------------------------------------------------------------
__global__ void wsplit_kernel(const float* __restrict__ W, int layer) {
    __shared__ float tile[32][33];
    int k0 = blockIdx.x * 32, n0 = blockIdx.y * 32;
    for (int i = threadIdx.y; i < 32; i += 8)
        tile[i][threadIdx.x] = W[(size_t)(k0 + i) * D + n0 + threadIdx.x];
    __syncthreads();
    for (int i = threadIdx.y; i < 32; i += 8) {
        float x = tile[threadIdx.x][i];                       // W[k0+tx][n0+i]
        __nv_bfloat16 hi = __float2bfloat16(x);
        float r = x - __bfloat162float(hi);
        size_t idx = (size_t)layer * D * D + (size_t)(n0 + i) * D + (k0 + threadIdx.x);
        g_wt0[idx] = hi;
        g_wt1[idx] = __float2bfloat16(r);
    }
}

// ---------------------------------------------------------------------------
// CSR aggregation fused with in_norm scale + bf16 split
// ---------------------------------------------------------------------------
__global__ __launch_bounds__(128)
void agg_kernel(const float* __restrict__ h) {
    int node = blockIdx.x;
    int lane4 = threadIdx.x * 4;
    int beg = g_rowoff[node], end = g_rowoff[node + 1];
    float ax = 0.f, ay = 0.f, az = 0.f, aw = 0.f;
    for (int e = beg; e < end; ++e) {
        int s = g_csr[e];
        float w = g_onorm[s];
        float4 v = *reinterpret_cast<const float4*>(&h[(size_t)s * D + lane4]);
        ax = fmaf(v.x, w, ax); ay = fmaf(v.y, w, ay);
        az = fmaf(v.z, w, az); aw = fmaf(v.w, w, aw);
    }
    float sc = g_inorm[node];
    ax *= sc; ay *= sc; az *= sc; aw *= sc;

    __nv_bfloat162 h01 = __floats2bfloat162_rn(ax, ay);
    __nv_bfloat162 h23 = __floats2bfloat162_rn(az, aw);
    float rx = ax - __bfloat162float(__low2bfloat16(h01));
    float ry = ay - __bfloat162float(__high2bfloat16(h01));
    float rz = az - __bfloat162float(__low2bfloat16(h23));
    float rw = aw - __bfloat162float(__high2bfloat16(h23));
    __nv_bfloat162 l01 = __floats2bfloat162_rn(rx, ry);
    __nv_bfloat162 l23 = __floats2bfloat162_rn(rz, rw);

    size_t off = (size_t)node * D + lane4;
    uint2 hiword, loword;
    hiword.x = *reinterpret_cast<uint32_t*>(&h01);
    hiword.y = *reinterpret_cast<uint32_t*>(&h23);
    loword.x = *reinterpret_cast<uint32_t*>(&l01);
    loword.y = *reinterpret_cast<uint32_t*>(&l23);
    *reinterpret_cast<uint2*>(&g_a0[off]) = hiword;
    *reinterpret_cast<uint2*>(&g_a1[off]) = loword;
}

// ---------------------------------------------------------------------------
// HMMA GEMM: C[M,512] = (A0+A1) @ (B0+B1)^T + bias (opt ReLU), bf16x3.
// CTA 128x128, BK=32, 256 threads (8 warps, warp tile 32x64).
// cp.async double buffer; ldmatrix fragments; padded smem rows (80B).
// ---------------------------------------------------------------------------
#define BM 128
#define BN 128
#define BK 32
#define NCHUNK (D / BK)            // 16
#define PAD_K 40                   // elements per smem row (80 bytes)
#define TILE_BYTES (128 * PAD_K * 2)     // 10240
#define STAGE_BYTES (4 * TILE_BYTES)     // 40960 (A0,A1,B0,B1)
#define GEMM_SMEM (2 * STAGE_BYTES)      // 81920

__device__ __forceinline__ void gemm_load_stage(
    uint32_t sb, int c, int m0, int n0, int tid,
    const __nv_bfloat16* wt0, const __nv_bfloat16* wt1)
{
    int k0 = c * BK;
    uint32_t stb = sb + (c & 1) * STAGE_BYTES;
#pragma unroll
    for (int i = 0; i < 8; i++) {
        int id = tid + i * 256;
        int t = id >> 9;                 // tile: 0=A0 1=A1 2=B0 3=B1
        int r = (id >> 2) & 127;         // row within tile
        int kc = id & 3;                 // 16B chunk within BK
        uint32_t dst = stb + (uint32_t)t * TILE_BYTES + (uint32_t)r * (PAD_K * 2) + kc * 16;
        const __nv_bfloat16* g;
        int size = 16;
        if (t < 2) {
            int row = m0 + r;
            const __nv_bfloat16* base = (t == 0) ? g_a0 : g_a1;
            if (row >= N_NODES) { row = 0; size = 0; }
            g = base + (size_t)row * D + k0 + kc * 8;
        } else {
            const __nv_bfloat16* base = (t == 2) ? wt0 : wt1;
            g = base + (size_t)(n0 + r) * D + k0 + kc * 8;
        }
        cp_async_16(dst, g, size);
    }
    asm volatile("cp.async.commit_group;" ::: "memory");
}

__global__ __launch_bounds__(256)
void hgemm_kernel(const float* __restrict__ bias, float* __restrict__ C,
                  int layer, int relu)
{
    extern __shared__ char smem[];
    uint32_t sb = smem_u32(smem);
    int tid = threadIdx.x;
    int lane = tid & 31, wid = tid >> 5;
    int m0 = blockIdx.y * BM;
    int n0 = blockIdx.x * BN;
    int wm = (wid & 3) * 32;            // warp m offset (4 warps in M)
    int wn = (wid >> 2) * 64;           // warp n offset (2 warps in N)

    const __nv_bfloat16* wt0 = g_wt0 + (size_t)layer * D * D;
    const __nv_bfloat16* wt1 = g_wt1 + (size_t)layer * D * D;

    float acc[2][8][4];
#pragma unroll
    for (int i = 0; i < 2; i++)
#pragma unroll
        for (int j = 0; j < 8; j++)
#pragma unroll
            for (int k = 0; k < 4; k++) acc[i][j][k] = 0.0f;

    // ldmatrix per-lane address components
    int lrow = lane & 15;
    uint32_t lcolb = (uint32_t)(lane >> 4) * 16;   // byte offset of 8-col group

    gemm_load_stage(sb, 0, m0, n0, tid, wt0, wt1);

#pragma unroll 1
    for (int c = 0; c < NCHUNK; ++c) {
        __syncthreads();   // protect buffer being overwritten by next load
        if (c + 1 < NCHUNK) {
            gemm_load_stage(sb, c + 1, m0, n0, tid, wt0, wt1);
            asm volatile("cp.async.wait_group 1;" ::: "memory");
        } else {
            asm volatile("cp.async.wait_group 0;" ::: "memory");
        }
        __syncthreads();

        uint32_t stb = sb + (c & 1) * STAGE_BYTES;
        uint32_t a0t = stb;
        uint32_t a1t = stb + TILE_BYTES;
        uint32_t b0t = stb + 2 * TILE_BYTES;
        uint32_t b1t = stb + 3 * TILE_BYTES;

#pragma unroll
        for (int kk = 0; kk < BK; kk += 16) {
            uint32_t kb = (uint32_t)kk * 2 + lcolb;
            uint32_t af[2][4], ag[2][4], bf[4][4];
            // A0 fragments (two m16 tiles)
#pragma unroll
            for (int mi = 0; mi < 2; mi++)
                ldsm_x4(af[mi], a0t + (uint32_t)(wm + mi * 16 + lrow) * (PAD_K * 2) + kb);
            // B0 fragments (eight n8 tiles via four x4 loads)
#pragma unroll
            for (int nb = 0; nb < 4; nb++)
                ldsm_x4(bf[nb], b0t + (uint32_t)(wn + nb * 16 + lrow) * (PAD_K * 2) + kb);
            // A0 * B0
#pragma unroll
            for (int mi = 0; mi < 2; mi++)
#pragma unroll
                for (int nb = 0; nb < 4; nb++) {
                    mma_16816(acc[mi][nb * 2 + 0], af[mi], bf[nb][0], bf[nb][2]);
                    mma_16816(acc[mi][nb * 2 + 1], af[mi], bf[nb][1], bf[nb][3]);
                }
            // A1 fragments, A1 * B0
#pragma unroll
            for (int mi = 0; mi < 2; mi++)
                ldsm_x4(ag[mi], a1t + (uint32_t)(wm + mi * 16 + lrow) * (PAD_K * 2) + kb);
#pragma unroll
            for (int mi = 0; mi < 2; mi++)
#pragma unroll
                for (int nb = 0; nb < 4; nb++) {
                    mma_16816(acc[mi][nb * 2 + 0], ag[mi], bf[nb][0], bf[nb][2]);
                    mma_16816(acc[mi][nb * 2 + 1], ag[mi], bf[nb][1], bf[nb][3]);
                }
            // B1 fragments, A0 * B1
#pragma unroll
            for (int nb = 0; nb < 4; nb++)
                ldsm_x4(bf[nb], b1t + (uint32_t)(wn + nb * 16 + lrow) * (PAD_K * 2) + kb);
#pragma unroll
            for (int mi = 0; mi < 2; mi++)
#pragma unroll
                for (int nb = 0; nb < 4; nb++) {
                    mma_16816(acc[mi][nb * 2 + 0], af[mi], bf[nb][0], bf[nb][2]);
                    mma_16816(acc[mi][nb * 2 + 1], af[mi], bf[nb][1], bf[nb][3]);
                }
        }
    }

    // Epilogue
    int rbase = m0 + wm + (lane >> 2);
    int cbase = n0 + wn + (lane & 3) * 2;
#pragma unroll
    for (int mi = 0; mi < 2; mi++) {
#pragma unroll
        for (int ni = 0; ni < 8; ni++) {
            int col = cbase + ni * 8;
            float2 bv = *reinterpret_cast<const float2*>(&bias[col]);
            int r0 = rbase + mi * 16;
            int r1 = r0 + 8;
            float2 o0, o1;
            o0.x = acc[mi][ni][0] + bv.x; o0.y = acc[mi][ni][1] + bv.y;
            o1.x = acc[mi][ni][2] + bv.x; o1.y = acc[mi][ni][3] + bv.y;
            if (relu) {
                o0.x = fmaxf(o0.x, 0.f); o0.y = fmaxf(o0.y, 0.f);
                o1.x = fmaxf(o1.x, 0.f); o1.y = fmaxf(o1.y, 0.f);
            }
            if (r0 < N_NODES)
                *reinterpret_cast<float2*>(&C[(size_t)r0 * D + col]) = o0;
            if (r1 < N_NODES)
                *reinterpret_cast<float2*>(&C[(size_t)r1 * D + col]) = o1;
        }
    }
}

// ---------------------------------------------------------------------------
// Mean pool per graph (graphs are contiguous blocks of 1250 nodes)
// ---------------------------------------------------------------------------
__global__ void pool_kernel(float* __restrict__ out) {
    int g = blockIdx.x;
    int c = blockIdx.y * 128 + threadIdx.x;
    const float* base = g_h + (size_t)g * NODES_PER_GRAPH * D;
    float s0 = 0.f, s1 = 0.f;
#pragma unroll 4
    for (int i = 0; i < NODES_PER_GRAPH; i += 2) {
        s0 += base[(size_t)i * D + c];
        s1 += base[(size_t)(i + 1) * D + c];
    }
    out[g * D + c] = (s0 + s1) * (1.0f / (float)NODES_PER_GRAPH);
}

// ---------------------------------------------------------------------------
// Launch
// ---------------------------------------------------------------------------
extern "C" void kernel_launch(void* const* d_in, const int* in_sizes, int n_in,
                              void* d_out, int out_size) {
    const float* feat = (const float*)d_in[0];
    const int* src = (const int*)d_in[1];
    const int* dst = (const int*)d_in[2];
    const float* W[4] = {(const float*)d_in[4], (const float*)d_in[6],
                         (const float*)d_in[8], (const float*)d_in[10]};
    const float* B[4] = {(const float*)d_in[5], (const float*)d_in[7],
                         (const float*)d_in[9], (const float*)d_in[11]};
    float* out = (float*)d_out;

    float* h_ptr = nullptr;
    cudaGetSymbolAddress((void**)&h_ptr, g_h);

    cudaFuncSetAttribute(hgemm_kernel, cudaFuncAttributeMaxDynamicSharedMemorySize,
                         GEMM_SMEM);

    // Graph preprocessing (CSR by dst + norms)
    zero_deg_kernel<<<(N_NODES + 255) / 256, 256>>>();
    degree_kernel<<<(N_EDGES + 255) / 256, 256>>>(src, dst);
    norm_kernel<<<(N_NODES + 255) / 256, 256>>>();
    scan_kernel<<<1, 1024>>>();
    fill_kernel<<<(N_EDGES + 255) / 256, 256>>>(src, dst);

    // Weight transpose + bf16 split
    for (int l = 0; l < N_LAYERS; l++)
        wsplit_kernel<<<dim3(D / 32, D / 32), dim3(32, 8)>>>(W[l], l);

    dim3 gemm_grid(D / BN, (N_NODES + BM - 1) / BM);   // (4, 157)
    for (int l = 0; l < N_LAYERS; l++) {
        const float* hin = (l == 0) ? feat : h_ptr;
        agg_kernel<<<N_NODES, 128>>>(hin);
        hgemm_kernel<<<gemm_grid, 256, GEMM_SMEM>>>(B[l], h_ptr, l, l < 3 ? 1 : 0);
    }

    pool_kernel<<<dim3(N_GRAPHS, D / 128), 128>>>(out);
}